// round 1
// baseline (speedup 1.0000x reference)
#include <cuda_runtime.h>

#define BATCH      16384
#define NFIELDS    26
#define FIELD_DIM  100000
#define WARPS_PER_BLOCK 8
#define THREADS    256
#define NBLOCKS    1024

__global__ __launch_bounds__(THREADS) void mixdim_embbag_kernel(
    const int*   __restrict__ x,    // [B, 26]
    const float* __restrict__ t0,   // [800000, 64]
    const float* __restrict__ t1,   // [800000, 32]
    const float* __restrict__ t2,   // [1000000, 16]
    const float* __restrict__ W1,   // [64, 32]
    const float* __restrict__ b1,   // [64]
    const float* __restrict__ W2,   // [64, 16]
    const float* __restrict__ b2,   // [64]
    float*       __restrict__ out)  // [B, 64]
{
    // Transposed, float2-packed weights: sW1[k*32+l] = {W1[2l][k], W1[2l+1][k]}
    __shared__ float2 sW1[32 * 32];
    __shared__ float2 sW2[16 * 32];
    __shared__ float2 sB[32];

    const int tid = threadIdx.x;
    for (int i = tid; i < 32 * 32; i += THREADS) {
        int k = i >> 5, l = i & 31;
        sW1[i] = make_float2(W1[(2 * l) * 32 + k], W1[(2 * l + 1) * 32 + k]);
    }
    for (int i = tid; i < 16 * 32; i += THREADS) {
        int k = i >> 5, l = i & 31;
        sW2[i] = make_float2(W2[(2 * l) * 16 + k], W2[(2 * l + 1) * 16 + k]);
    }
    if (tid < 32) {
        // 8 fields in block1, 10 fields in block2 -> bias scaled by field count
        sB[tid] = make_float2(8.f * b1[2 * tid]     + 10.f * b2[2 * tid],
                              8.f * b1[2 * tid + 1] + 10.f * b2[2 * tid + 1]);
    }
    __syncthreads();

    const int warp = tid >> 5;
    const int lane = tid & 31;
    const unsigned FULL = 0xffffffffu;

    for (int row = blockIdx.x * WARPS_PER_BLOCK + warp; row < BATCH;
         row += gridDim.x * WARPS_PER_BLOCK)
    {
        int myidx = 0;
        if (lane < NFIELDS) myidx = x[row * NFIELDS + lane];

        // ---- issue ALL gathers first (maximize MLP) ----
        // block 0: fields 0..7, 64-dim rows -> float2 per lane (256B coalesced)
        float2 v0[8];
        #pragma unroll
        for (int f = 0; f < 8; f++) {
            int idx = __shfl_sync(FULL, myidx, f) + f * FIELD_DIM;
            v0[f] = ((const float2*)(t0 + (long long)idx * 64))[lane];
        }
        // block 1: fields 8..15, 32-dim rows -> 1 float per lane (128B coalesced)
        float v1[8];
        #pragma unroll
        for (int f = 0; f < 8; f++) {
            int idx = __shfl_sync(FULL, myidx, 8 + f) + f * FIELD_DIM;
            v1[f] = t1[(long long)idx * 32 + lane];
        }
        // block 2: fields 16..25, 16-dim rows -> two rows per warp-load
        const int half = lane >> 4;       // 0: even field of pair, 1: odd
        const int l16  = lane & 15;
        float v2[5];
        #pragma unroll
        for (int p = 0; p < 5; p++) {
            int f = 2 * p + half;         // 0..9
            int idx = __shfl_sync(FULL, myidx, 16 + f) + f * FIELD_DIM;
            v2[p] = t2[(long long)idx * 16 + l16];
        }

        // ---- reductions ----
        float2 acc = sB[lane];
        #pragma unroll
        for (int f = 0; f < 8; f++) { acc.x += v0[f].x; acc.y += v0[f].y; }

        float s1 = 0.f;
        #pragma unroll
        for (int f = 0; f < 8; f++) s1 += v1[f];

        float s2 = 0.f;
        #pragma unroll
        for (int p = 0; p < 5; p++) s2 += v2[p];
        s2 += __shfl_xor_sync(FULL, s2, 16);   // lane k (k<16) now has full s2[k]

        // ---- projections: out[o] += sum_k W[o][k] * s[k] ----
        #pragma unroll
        for (int k = 0; k < 32; k++) {
            float v  = __shfl_sync(FULL, s1, k);
            float2 w = sW1[k * 32 + lane];
            acc.x += w.x * v; acc.y += w.y * v;
        }
        #pragma unroll
        for (int k = 0; k < 16; k++) {
            float v  = __shfl_sync(FULL, s2, k);
            float2 w = sW2[k * 32 + lane];
            acc.x += w.x * v; acc.y += w.y * v;
        }

        ((float2*)(out + (long long)row * 64))[lane] = acc;
    }
}

extern "C" void kernel_launch(void* const* d_in, const int* in_sizes, int n_in,
                              void* d_out, int out_size)
{
    const int*   x  = (const int*)  d_in[0];
    const float* t0 = (const float*)d_in[1];
    const float* t1 = (const float*)d_in[2];
    const float* t2 = (const float*)d_in[3];
    const float* W1 = (const float*)d_in[4];
    const float* b1 = (const float*)d_in[5];
    const float* W2 = (const float*)d_in[6];
    const float* b2 = (const float*)d_in[7];
    float* out = (float*)d_out;

    mixdim_embbag_kernel<<<NBLOCKS, THREADS>>>(x, t0, t1, t2, W1, b1, W2, b2, out);
}

// round 2
// speedup vs baseline: 1.4337x; 1.4337x over previous
#include <cuda_runtime.h>

#define BATCH      16384
#define FIELD_DIM  100000

// scratch: per-row [s1(32) | s2(16)] block sums, packed 48 floats/row
__device__ float g_scratch[BATCH * 48];

// ---------------------------------------------------------------------------
// Kernel A: pure gather + segment-sum. One warp per row. No shared memory.
// ---------------------------------------------------------------------------
__global__ __launch_bounds__(256) void gather_kernel(
    const int*   __restrict__ x,    // [B, 26]
    const float* __restrict__ t0,   // [800000, 64]
    const float* __restrict__ t1,   // [800000, 32]
    const float* __restrict__ t2,   // [1000000, 16]
    float*       __restrict__ out)  // [B, 64]  (block0 partial sum)
{
    const int warp = threadIdx.x >> 5;
    const int lane = threadIdx.x & 31;
    const unsigned FULL = 0xffffffffu;

    for (int row = blockIdx.x * 8 + warp; row < BATCH; row += gridDim.x * 8)
    {
        int myidx = 0;
        if (lane < 26) myidx = x[row * 26 + lane];

        // ---- issue ALL gathers back-to-back for max MLP ----
        // block 0: 8 fields, 64-dim rows -> float2/lane (256B coalesced)
        float2 v0[8];
        #pragma unroll
        for (int f = 0; f < 8; f++) {
            int idx = __shfl_sync(FULL, myidx, f) + f * FIELD_DIM;
            v0[f] = ((const float2*)(t0 + (long long)idx * 64))[lane];
        }
        // block 1: 8 fields, 32-dim rows -> 1 float/lane (128B coalesced)
        float v1[8];
        #pragma unroll
        for (int f = 0; f < 8; f++) {
            int idx = __shfl_sync(FULL, myidx, 8 + f) + f * FIELD_DIM;
            v1[f] = t1[(long long)idx * 32 + lane];
        }
        // block 2: 10 fields, 16-dim rows -> two rows per warp-load (half-warps)
        const int half = lane >> 4;
        const int l16  = lane & 15;
        float v2[5];
        #pragma unroll
        for (int p = 0; p < 5; p++) {
            int f = 2 * p + half;
            int idx = __shfl_sync(FULL, myidx, 16 + f) + f * FIELD_DIM;
            v2[p] = t2[(long long)idx * 16 + l16];
        }

        // ---- reductions ----
        float2 acc = make_float2(0.f, 0.f);
        #pragma unroll
        for (int f = 0; f < 8; f++) { acc.x += v0[f].x; acc.y += v0[f].y; }

        float s1 = 0.f;
        #pragma unroll
        for (int f = 0; f < 8; f++) s1 += v1[f];

        float s2 = 0.f;
        #pragma unroll
        for (int p = 0; p < 5; p++) s2 += v2[p];
        s2 += __shfl_xor_sync(FULL, s2, 16);   // lanes 0..15 (and 16..31) hold full s2

        // ---- stores (all coalesced) ----
        ((float2*)(out + (long long)row * 64))[lane] = acc;      // 256B
        g_scratch[row * 48 + lane] = s1;                          // 128B
        if (lane < 16) g_scratch[row * 48 + 32 + lane] = s2;      // 64B
    }
}

// ---------------------------------------------------------------------------
// Kernel B: out[B,64] += S[B,48] @ Wt[48,64] + bias.  64 rows/block.
// Each warp: 8 rows x 64 outputs (lane owns output pair 2l,2l+1).
// ---------------------------------------------------------------------------
__global__ __launch_bounds__(256) void proj_kernel(
    const float* __restrict__ W1,   // [64, 32]
    const float* __restrict__ b1,   // [64]
    const float* __restrict__ W2,   // [64, 16]
    const float* __restrict__ b2,   // [64]
    float*       __restrict__ out)  // [B, 64]
{
    __shared__ float2 sW[48][32];       // sW[k][l] = {W[2l][k], W[2l+1][k]}
    __shared__ float2 sBias[32];
    __shared__ float  sS[64 * 48];      // this block's 64 rows of S

    const int tid = threadIdx.x;

    #pragma unroll 2
    for (int i = tid; i < 48 * 32; i += 256) {
        int k = i >> 5, l = i & 31;
        float a, b;
        if (k < 32) { a = W1[(2 * l) * 32 + k];        b = W1[(2 * l + 1) * 32 + k]; }
        else        { a = W2[(2 * l) * 16 + (k - 32)]; b = W2[(2 * l + 1) * 16 + (k - 32)]; }
        sW[k][l] = make_float2(a, b);
    }
    if (tid < 32)
        sBias[tid] = make_float2(8.f * b1[2 * tid]     + 10.f * b2[2 * tid],
                                 8.f * b1[2 * tid + 1] + 10.f * b2[2 * tid + 1]);

    // coalesced copy of 64 rows x 48 floats = 768 float4
    {
        const float4* src = (const float4*)(g_scratch + (long long)blockIdx.x * 64 * 48);
        float4* dst = (float4*)sS;
        #pragma unroll
        for (int i = tid; i < 768; i += 256) dst[i] = src[i];
    }
    __syncthreads();

    const int warp = tid >> 5;
    const int lane = tid & 31;
    const int row0 = blockIdx.x * 64 + warp * 8;

    float2 acc[8];
    const float2 bias = sBias[lane];
    #pragma unroll
    for (int r = 0; r < 8; r++) {
        float2 p = ((const float2*)(out + (long long)(row0 + r) * 64))[lane];
        acc[r] = make_float2(p.x + bias.x, p.y + bias.y);
    }

    #pragma unroll
    for (int k = 0; k < 48; k += 4) {
        float2 w0 = sW[k + 0][lane];
        float2 w1 = sW[k + 1][lane];
        float2 w2 = sW[k + 2][lane];
        float2 w3 = sW[k + 3][lane];
        #pragma unroll
        for (int r = 0; r < 8; r++) {
            float4 s4 = *(const float4*)&sS[(warp * 8 + r) * 48 + k];  // warp-uniform broadcast
            acc[r].x += s4.x * w0.x; acc[r].y += s4.x * w0.y;
            acc[r].x += s4.y * w1.x; acc[r].y += s4.y * w1.y;
            acc[r].x += s4.z * w2.x; acc[r].y += s4.z * w2.y;
            acc[r].x += s4.w * w3.x; acc[r].y += s4.w * w3.y;
        }
    }

    #pragma unroll
    for (int r = 0; r < 8; r++)
        ((float2*)(out + (long long)(row0 + r) * 64))[lane] = acc[r];
}

extern "C" void kernel_launch(void* const* d_in, const int* in_sizes, int n_in,
                              void* d_out, int out_size)
{
    const int*   x  = (const int*)  d_in[0];
    const float* t0 = (const float*)d_in[1];
    const float* t1 = (const float*)d_in[2];
    const float* t2 = (const float*)d_in[3];
    const float* W1 = (const float*)d_in[4];
    const float* b1 = (const float*)d_in[5];
    const float* W2 = (const float*)d_in[6];
    const float* b2 = (const float*)d_in[7];
    float* out = (float*)d_out;

    gather_kernel<<<1024, 256>>>(x, t0, t1, t2, out);
    proj_kernel<<<BATCH / 64, 256>>>(W1, b1, W2, b2, out);
}